// round 6
// baseline (speedup 1.0000x reference)
#include <cuda_runtime.h>
#include <cstdint>

// Log-signature depth 3, d=8, L=256, B=2048.
// Chunked scan (4 chunks/path, Chen tree-combine) + packed f32x2 inner loop.
// R5: register diet — no persistent start-point regs (S1 via epilogue reload),
// unroll 2, launch_bounds(256,3) for 24 warps/SM; pad-select hoisted out of
// the hot loop.

#define BATCH   2048
#define LPATH   256
#define DCH     8
#define OUT_PB  584
#define TPB     256            // 16 groups = 4 batches x 4 chunks
#define BPB     4
#define SIGSZ   656            // 8 + 8x9 (S2) + 64x9 (S3)

using u64 = unsigned long long;

__device__ __forceinline__ u64 pack2(float lo, float hi) {
    u64 r; asm("mov.b64 %0, {%1, %2};" : "=l"(r) : "f"(lo), "f"(hi)); return r;
}
__device__ __forceinline__ void unpack2(u64 v, float& lo, float& hi) {
    asm("mov.b64 {%0, %1}, %2;" : "=f"(lo), "=f"(hi) : "l"(v));
}
__device__ __forceinline__ u64 fma2(u64 a, u64 b, u64 c) {
    u64 d; asm("fma.rn.f32x2 %0, %1, %2, %3;" : "=l"(d) : "l"(a), "l"(b), "l"(c)); return d;
}

__global__ __launch_bounds__(TPB, 3)
void logsig_kernel(const float* __restrict__ x, float* __restrict__ out)
{
    const int tid  = threadIdx.x;
    const int lane = tid & 31;
    const int s    = lane & 15;
    const int i    = s >> 1;
    const bool hib = (s & 1) != 0;
    const int jb   = hib ? 4 : 0;

    const int gid   = tid >> 4;
    const int bL    = gid >> 2;
    const int chunk = gid & 3;
    const long b = (long)blockIdx.x * BPB + bL;

    const int start = chunk * 64;
    const float* xf = x + ((size_t)b * LPATH + start) * DCH;
    const longlong2* xv = reinterpret_cast<const longlong2*>(xf);

    const u64 NEG1 = pack2(-1.0f, -1.0f);

    u64 S3p[4][4];
#pragma unroll
    for (int q = 0; q < 4; ++q)
#pragma unroll
        for (int kp = 0; kp < 4; ++kp) S3p[q][kp] = 0ull;
    u64 S2p0 = 0ull, S2p1 = 0ull;
    float S1i = 0.0f;

    longlong2 v0 = __ldg(xv);
    longlong2 v1 = __ldg(xv + 1);
    u64 xp0 = (u64)v0.x, xp1 = (u64)v0.y, xp2 = (u64)v1.x, xp3 = (u64)v1.y;
    float xli = __ldg(xf + i);

    auto step = [&](int tt) {
        longlong2 va = __ldg(xv + 2 * tt);
        longlong2 vb = __ldg(xv + 2 * tt + 1);
        float yi = __ldg(xf + (size_t)tt * DCH + i);

        u64 d0 = fma2(xp0, NEG1, (u64)va.x);
        u64 d1 = fma2(xp1, NEG1, (u64)va.y);
        u64 d2 = fma2(xp2, NEG1, (u64)vb.x);
        u64 d3 = fma2(xp3, NEG1, (u64)vb.y);
        xp0 = (u64)va.x; xp1 = (u64)va.y; xp2 = (u64)vb.x; xp3 = (u64)vb.y;

        float dxi = yi - xli; xli = yi;
        float av = fmaf(dxi, 1.0f / 6.0f, 0.5f * S1i);   // old S1i
        float bv = fmaf(dxi, 0.5f, S1i);
        S1i += dxi;
        u64 a2 = pack2(av, av);
        u64 b2 = pack2(bv, bv);

        u64 dj01 = hib ? d2 : d0;
        u64 dj23 = hib ? d3 : d1;

        u64 m01 = fma2(a2, dj01, S2p0);                  // old S2
        u64 m23 = fma2(a2, dj23, S2p1);
        S2p0 = fma2(b2, dj01, S2p0);
        S2p1 = fma2(b2, dj23, S2p1);

        float m0, m1, m2, m3;
        unpack2(m01, m0, m1); unpack2(m23, m2, m3);
        u64 M0 = pack2(m0, m0), M1 = pack2(m1, m1);
        u64 M2 = pack2(m2, m2), M3 = pack2(m3, m3);

        S3p[0][0] = fma2(M0, d0, S3p[0][0]);
        S3p[0][1] = fma2(M0, d1, S3p[0][1]);
        S3p[0][2] = fma2(M0, d2, S3p[0][2]);
        S3p[0][3] = fma2(M0, d3, S3p[0][3]);
        S3p[1][0] = fma2(M1, d0, S3p[1][0]);
        S3p[1][1] = fma2(M1, d1, S3p[1][1]);
        S3p[1][2] = fma2(M1, d2, S3p[1][2]);
        S3p[1][3] = fma2(M1, d3, S3p[1][3]);
        S3p[2][0] = fma2(M2, d0, S3p[2][0]);
        S3p[2][1] = fma2(M2, d1, S3p[2][1]);
        S3p[2][2] = fma2(M2, d2, S3p[2][2]);
        S3p[2][3] = fma2(M2, d3, S3p[2][3]);
        S3p[3][0] = fma2(M3, d0, S3p[3][0]);
        S3p[3][1] = fma2(M3, d1, S3p[3][1]);
        S3p[3][2] = fma2(M3, d2, S3p[3][2]);
        S3p[3][3] = fma2(M3, d3, S3p[3][3]);
    };

#pragma unroll 2
    for (int t = 1; t < 64; ++t) step(t);
    // final step: chunk 3 has only 63 real increments -> redo point 63 (dx=0 identity)
    step(chunk == 3 ? 63 : 64);

    // ---- unpack scan state to scalars ----
    float S3f[4][8];
#pragma unroll
    for (int q = 0; q < 4; ++q)
#pragma unroll
        for (int kp = 0; kp < 4; ++kp)
            unpack2(S3p[q][kp], S3f[q][2 * kp], S3f[q][2 * kp + 1]);
    float S2f[4];
    unpack2(S2p0, S2f[0], S2f[1]);
    unpack2(S2p1, S2f[2], S2f[3]);

    // S1 = x_end - x_start (reload start; L2/L1 hot)
    float S1f[8];
    {
        longlong2 r0 = __ldg(xv);
        longlong2 r1 = __ldg(xv + 1);
        u64 q0 = fma2((u64)r0.x, NEG1, xp0); unpack2(q0, S1f[0], S1f[1]);
        u64 q1 = fma2((u64)r0.y, NEG1, xp1); unpack2(q1, S1f[2], S1f[3]);
        u64 q2 = fma2((u64)r1.x, NEG1, xp2); unpack2(q2, S1f[4], S1f[5]);
        u64 q3 = fma2((u64)r1.y, NEG1, xp3); unpack2(q3, S1f[6], S1f[7]);
    }

    // ---------------- Chen tree-combine via shared memory ----------------
    __shared__ float sig[BPB][4][SIGSZ];

    auto store_sig = [&](float* p) {
        if (s == 0) {
#pragma unroll
            for (int k = 0; k < 8; ++k) p[k] = S1f[k];
        }
#pragma unroll
        for (int q = 0; q < 4; ++q)
            p[8 + i * 9 + jb + q] = S2f[q];
#pragma unroll
        for (int q = 0; q < 4; ++q)
#pragma unroll
            for (int k = 0; k < 8; ++k)
                p[80 + (i * 8 + jb + q) * 9 + k] = S3f[q][k];
    };

    auto combine = [&](const float* p) {   // regs = earlier part a, p = later part b
        float S1b[8];
#pragma unroll
        for (int k = 0; k < 8; ++k) S1b[k] = p[k];
#pragma unroll
        for (int q = 0; q < 4; ++q) {
            const float* s2row = p + 8 + (jb + q) * 9;            // S2b[j,:]
            const float* s3row = p + 80 + (i * 8 + jb + q) * 9;   // S3b[i,j,:]
#pragma unroll
            for (int k = 0; k < 8; ++k)
                S3f[q][k] += S2f[q] * S1b[k] + S1i * s2row[k] + s3row[k];
            float S1bj = hib ? S1b[4 + q] : S1b[q];
            S2f[q] += S1i * S1bj + p[8 + i * 9 + jb + q];
        }
#pragma unroll
        for (int k = 0; k < 8; ++k) S1f[k] += S1b[k];
        S1i += p[i];
    };

    if (chunk == 1 || chunk == 3) store_sig(&sig[bL][chunk][0]);
    __syncthreads();
    if (chunk == 0) {
        combine(&sig[bL][1][0]);
    } else if (chunk == 2) {
        combine(&sig[bL][3][0]);
        store_sig(&sig[bL][2][0]);
    }
    __syncthreads();
    if (chunk != 0) return;          // chunk-0 groups are always lanes 0-15

    combine(&sig[bL][2][0]);

    // ---------------- log projection + writeback ----------------
    float* p0 = &sig[bL][0][0];
#pragma unroll
    for (int q = 0; q < 4; ++q)
        p0[8 + i * 9 + jb + q] = S2f[q];   // publish full S2 for [j,k] reads
    __syncwarp(0x0000FFFFu);

    float* ob = out + (size_t)b * OUT_PB;

    // l1
    if (s == 0) {
        *reinterpret_cast<float4*>(ob)     = make_float4(S1f[0], S1f[1], S1f[2], S1f[3]);
        *reinterpret_cast<float4*>(ob + 4) = make_float4(S1f[4], S1f[5], S1f[6], S1f[7]);
    }

    // l2 = S2 - 0.5 S1 x S1
    {
        float4 v; float* vv = &v.x;
#pragma unroll
        for (int q = 0; q < 4; ++q) {
            float S1j = hib ? S1f[4 + q] : S1f[q];
            vv[q] = S2f[q] - 0.5f * S1i * S1j;
        }
        *reinterpret_cast<float4*>(ob + 8 + 4 * s) = v;
    }

    // l3 = S3 - 0.5 (S1_i S2[j,k] + S2[i,j] S1_k) + (1/3) S1_i S1_j S1_k
#pragma unroll
    for (int q = 0; q < 4; ++q) {
        float S1j  = hib ? S1f[4 + q] : S1f[q];
        float S2ij = S2f[q];
        float tij  = (1.0f / 3.0f) * S1i * S1j;
        const float* row = p0 + 8 + (jb + q) * 9;    // S2[j,:]
        float4 lo, hi4;
        float* lv = &lo.x; float* hv = &hi4.x;
#pragma unroll
        for (int k = 0; k < 8; ++k) {
            float val = S3f[q][k]
                      - 0.5f * (S1i * row[k] + S2ij * S1f[k])
                      + tij * S1f[k];
            if (k < 4) lv[k] = val; else hv[k - 4] = val;
        }
        float* dst = ob + 72 + 32 * s + 8 * q;
        *reinterpret_cast<float4*>(dst)     = lo;
        *reinterpret_cast<float4*>(dst + 4) = hi4;
    }
}

extern "C" void kernel_launch(void* const* d_in, const int* in_sizes, int n_in,
                              void* d_out, int out_size)
{
    const float* x = (const float*)d_in[0];
    float* out = (float*)d_out;
    (void)in_sizes; (void)n_in; (void)out_size;

    const int blocks = BATCH / BPB;   // 512
    logsig_kernel<<<blocks, TPB>>>(x, out);
}

// round 7
// speedup vs baseline: 1.3381x; 1.3381x over previous
#include <cuda_runtime.h>
#include <cstdint>

// Log-signature depth 3, d=8, L=256, B=2048.
// R6: dx staged in shared memory (computed cooperatively from GMEM), scan
// reads packed dx via LDS.128 -> no prev-point registers, no per-step
// subtraction, uniform 64-step chunks. smem dx buffer aliased with the Chen
// combine sig buffer. launch_bounds(256,3) for 24 warps/SM.
//
// Group layout (16 lanes / chunk): lane s owns i = s>>1, j in {jb..jb+3},
// jb=(s&1)*4. S2 = 2 f32x2 regs, S3 = 16 f32x2 regs.
// Step (old state on RHS):
//   m_q  = S2[i,j] + (0.5*S1_i + dx_i/6) * dx_j
//   S3  += m_q (x) dx            (16 fma.rn.f32x2)
//   S2  += (S1_i + 0.5*dx_i) * dx_j

#define BATCH   2048
#define LPATH   256
#define DCH     8
#define OUT_PB  584
#define TPB     256            // 16 groups = 4 batches x 4 chunks
#define BPB     4
#define SIGSZ   656            // 8 + 8x9 (S2) + 64x9 (S3)
#define DXS     2052           // floats per batch dx region (8*256 + 4 pad)
#define SMEMF   10496          // max(4*DXS=8208, 16*SIGSZ=10496)

using u64 = unsigned long long;

__device__ __forceinline__ u64 pack2(float lo, float hi) {
    u64 r; asm("mov.b64 %0, {%1, %2};" : "=l"(r) : "f"(lo), "f"(hi)); return r;
}
__device__ __forceinline__ void unpack2(u64 v, float& lo, float& hi) {
    asm("mov.b64 {%0, %1}, %2;" : "=f"(lo), "=f"(hi) : "l"(v));
}
__device__ __forceinline__ u64 fma2(u64 a, u64 b, u64 c) {
    u64 d; asm("fma.rn.f32x2 %0, %1, %2, %3;" : "=l"(d) : "l"(a), "l"(b), "l"(c)); return d;
}

__global__ __launch_bounds__(TPB, 3)
void logsig_kernel(const float* __restrict__ x, float* __restrict__ out)
{
    __shared__ __align__(16) float smem[SMEMF];

    const int tid  = threadIdx.x;
    const int lane = tid & 31;
    const int s    = lane & 15;
    const int i    = s >> 1;
    const bool hib = (s & 1) != 0;
    const int jb   = hib ? 4 : 0;

    const int gid   = tid >> 4;
    const int bL    = gid >> 2;
    const int chunk = gid & 3;
    const long b = (long)blockIdx.x * BPB + bL;
    const int start = chunk * 64;

    // ---------------- phase 1: dx -> shared (padded, dx[255]=0) ----------
    {
        const float4* xg = reinterpret_cast<const float4*>(
            x + (size_t)blockIdx.x * BPB * LPATH * DCH);
#pragma unroll 2
        for (int k = 0; k < 8; ++k) {
            int e  = tid + 256 * k;        // 0..2047 : (batch, point, half)
            int bb = e >> 9;
            int r  = e & 511;
            int t  = r >> 1;
            int h  = r & 1;
            int tn = (t < 255) ? t + 1 : 255;     // pad point -> dx = 0
            const float4* xb4 = xg + bb * 512;
            float4 cur = __ldg(xb4 + 2 * t  + h);
            float4 nxt = __ldg(xb4 + 2 * tn + h);
            float4 dv;
            dv.x = nxt.x - cur.x; dv.y = nxt.y - cur.y;
            dv.z = nxt.z - cur.z; dv.w = nxt.w - cur.w;
            *reinterpret_cast<float4*>(&smem[bb * DXS + t * 8 + h * 4]) = dv;
        }
    }
    __syncthreads();

    // ---------------- phase 2: 64-step packed scan from smem -------------
    u64 S3p[4][4];
#pragma unroll
    for (int q = 0; q < 4; ++q)
#pragma unroll
        for (int kp = 0; kp < 4; ++kp) S3p[q][kp] = 0ull;
    u64 S2p0 = 0ull, S2p1 = 0ull;
    float S1i = 0.0f;

    const float* dxp = &smem[bL * DXS + start * 8];
    const longlong2* dv2 = reinterpret_cast<const longlong2*>(dxp);

#pragma unroll 4
    for (int t = 0; t < 64; ++t) {
        longlong2 va = dv2[2 * t];
        longlong2 vb = dv2[2 * t + 1];
        float dxi = dxp[t * 8 + i];

        u64 d0 = (u64)va.x, d1 = (u64)va.y, d2 = (u64)vb.x, d3 = (u64)vb.y;

        float av = fmaf(dxi, 1.0f / 6.0f, 0.5f * S1i);   // old S1i
        float bv = fmaf(dxi, 0.5f, S1i);
        S1i += dxi;
        u64 a2 = pack2(av, av);
        u64 b2 = pack2(bv, bv);

        u64 dj01 = hib ? d2 : d0;
        u64 dj23 = hib ? d3 : d1;

        u64 m01 = fma2(a2, dj01, S2p0);                  // old S2
        u64 m23 = fma2(a2, dj23, S2p1);
        S2p0 = fma2(b2, dj01, S2p0);
        S2p1 = fma2(b2, dj23, S2p1);

        float m0, m1, m2, m3;
        unpack2(m01, m0, m1); unpack2(m23, m2, m3);
        u64 M0 = pack2(m0, m0), M1 = pack2(m1, m1);
        u64 M2 = pack2(m2, m2), M3 = pack2(m3, m3);

        S3p[0][0] = fma2(M0, d0, S3p[0][0]);
        S3p[0][1] = fma2(M0, d1, S3p[0][1]);
        S3p[0][2] = fma2(M0, d2, S3p[0][2]);
        S3p[0][3] = fma2(M0, d3, S3p[0][3]);
        S3p[1][0] = fma2(M1, d0, S3p[1][0]);
        S3p[1][1] = fma2(M1, d1, S3p[1][1]);
        S3p[1][2] = fma2(M1, d2, S3p[1][2]);
        S3p[1][3] = fma2(M1, d3, S3p[1][3]);
        S3p[2][0] = fma2(M2, d0, S3p[2][0]);
        S3p[2][1] = fma2(M2, d1, S3p[2][1]);
        S3p[2][2] = fma2(M2, d2, S3p[2][2]);
        S3p[2][3] = fma2(M2, d3, S3p[2][3]);
        S3p[3][0] = fma2(M3, d0, S3p[3][0]);
        S3p[3][1] = fma2(M3, d1, S3p[3][1]);
        S3p[3][2] = fma2(M3, d2, S3p[3][2]);
        S3p[3][3] = fma2(M3, d3, S3p[3][3]);
    }

    // ---- unpack scan state; S1 via telescoped endpoints (GMEM, L2-hot) --
    float S3f[4][8];
#pragma unroll
    for (int q = 0; q < 4; ++q)
#pragma unroll
        for (int kp = 0; kp < 4; ++kp)
            unpack2(S3p[q][kp], S3f[q][2 * kp], S3f[q][2 * kp + 1]);
    float S2f[4];
    unpack2(S2p0, S2f[0], S2f[1]);
    unpack2(S2p1, S2f[2], S2f[3]);

    float S1f[8];
    {
        const float4* xg2 = reinterpret_cast<const float4*>(
            x + (size_t)b * LPATH * DCH);
        int pend = (chunk == 3) ? 255 : (start + 64);
        float4 e0 = __ldg(xg2 + 2 * pend);
        float4 e1 = __ldg(xg2 + 2 * pend + 1);
        float4 s0 = __ldg(xg2 + 2 * start);
        float4 s1 = __ldg(xg2 + 2 * start + 1);
        S1f[0] = e0.x - s0.x; S1f[1] = e0.y - s0.y;
        S1f[2] = e0.z - s0.z; S1f[3] = e0.w - s0.w;
        S1f[4] = e1.x - s1.x; S1f[5] = e1.y - s1.y;
        S1f[6] = e1.z - s1.z; S1f[7] = e1.w - s1.w;
    }

    // ---------------- Chen tree-combine (smem aliased over dx) -----------
    __syncthreads();                       // dx buffer is dead from here on
    float (*sig)[SIGSZ] = reinterpret_cast<float (*)[SIGSZ]>(smem);

    auto store_sig = [&](float* p) {
        if (s == 0) {
#pragma unroll
            for (int k = 0; k < 8; ++k) p[k] = S1f[k];
        }
#pragma unroll
        for (int q = 0; q < 4; ++q)
            p[8 + i * 9 + jb + q] = S2f[q];
#pragma unroll
        for (int q = 0; q < 4; ++q)
#pragma unroll
            for (int k = 0; k < 8; ++k)
                p[80 + (i * 8 + jb + q) * 9 + k] = S3f[q][k];
    };

    auto combine = [&](const float* p) {   // regs = earlier part a, p = later part b
        float S1b[8];
#pragma unroll
        for (int k = 0; k < 8; ++k) S1b[k] = p[k];
#pragma unroll
        for (int q = 0; q < 4; ++q) {
            const float* s2row = p + 8 + (jb + q) * 9;            // S2b[j,:]
            const float* s3row = p + 80 + (i * 8 + jb + q) * 9;   // S3b[i,j,:]
#pragma unroll
            for (int k = 0; k < 8; ++k)
                S3f[q][k] += S2f[q] * S1b[k] + S1i * s2row[k] + s3row[k];
            float S1bj = hib ? S1b[4 + q] : S1b[q];
            S2f[q] += S1i * S1bj + p[8 + i * 9 + jb + q];
        }
#pragma unroll
        for (int k = 0; k < 8; ++k) S1f[k] += S1b[k];
        S1i += p[i];
    };

    if (chunk == 1 || chunk == 3) store_sig(&sig[bL * 4 + chunk][0]);
    __syncthreads();
    if (chunk == 0) {
        combine(&sig[bL * 4 + 1][0]);
    } else if (chunk == 2) {
        combine(&sig[bL * 4 + 3][0]);
        store_sig(&sig[bL * 4 + 2][0]);
    }
    __syncthreads();
    if (chunk != 0) return;          // chunk-0 groups are always lanes 0-15

    combine(&sig[bL * 4 + 2][0]);

    // ---------------- log projection + writeback ----------------
    float* p0 = &sig[bL * 4 + 0][0];
#pragma unroll
    for (int q = 0; q < 4; ++q)
        p0[8 + i * 9 + jb + q] = S2f[q];   // publish full S2 for [j,k] reads
    __syncwarp(0x0000FFFFu);

    float* ob = out + (size_t)b * OUT_PB;

    // l1
    if (s == 0) {
        *reinterpret_cast<float4*>(ob)     = make_float4(S1f[0], S1f[1], S1f[2], S1f[3]);
        *reinterpret_cast<float4*>(ob + 4) = make_float4(S1f[4], S1f[5], S1f[6], S1f[7]);
    }

    // l2 = S2 - 0.5 S1 x S1
    {
        float4 v; float* vv = &v.x;
#pragma unroll
        for (int q = 0; q < 4; ++q) {
            float S1j = hib ? S1f[4 + q] : S1f[q];
            vv[q] = S2f[q] - 0.5f * S1i * S1j;
        }
        *reinterpret_cast<float4*>(ob + 8 + 4 * s) = v;
    }

    // l3 = S3 - 0.5 (S1_i S2[j,k] + S2[i,j] S1_k) + (1/3) S1_i S1_j S1_k
#pragma unroll
    for (int q = 0; q < 4; ++q) {
        float S1j  = hib ? S1f[4 + q] : S1f[q];
        float S2ij = S2f[q];
        float tij  = (1.0f / 3.0f) * S1i * S1j;
        const float* row = p0 + 8 + (jb + q) * 9;    // S2[j,:]
        float4 lo, hi4;
        float* lv = &lo.x; float* hv = &hi4.x;
#pragma unroll
        for (int k = 0; k < 8; ++k) {
            float val = S3f[q][k]
                      - 0.5f * (S1i * row[k] + S2ij * S1f[k])
                      + tij * S1f[k];
            if (k < 4) lv[k] = val; else hv[k - 4] = val;
        }
        float* dst = ob + 72 + 32 * s + 8 * q;
        *reinterpret_cast<float4*>(dst)     = lo;
        *reinterpret_cast<float4*>(dst + 4) = hi4;
    }
}

extern "C" void kernel_launch(void* const* d_in, const int* in_sizes, int n_in,
                              void* d_out, int out_size)
{
    const float* x = (const float*)d_in[0];
    float* out = (float*)d_out;
    (void)in_sizes; (void)n_in; (void)out_size;

    const int blocks = BATCH / BPB;   // 512
    logsig_kernel<<<blocks, TPB>>>(x, out);
}